// round 10
// baseline (speedup 1.0000x reference)
#include <cuda_runtime.h>
#include <cuda_fp16.h>
#include <cstdint>

#define BATCH   4096
#define DIM     1024
#define NSAMP   32768
#define MT      128
#define NT      128
#define KC      64                   // K chunk (fp16) = 128B row
#define NKC     (DIM / KC)           // 16
#define MTILES  (BATCH / MT)         // 32
#define NTILES  (NSAMP / NT)         // 256
#define TOTTILES (MTILES * NTILES)   // 8192
#define GRID    296                  // 148 SMs x 2 CTAs, persistent
#define BLKB    16384                // one (tile, chunk) block: 128 rows x 128B
#define STG     (2 * BLKB)           // A + B per stage = 32KB
#define SMEM_DYN (3 * STG)           // 96KB
#define TEMP_INV 20.0f
#define EXP_SCALE (20.0f * 1.4426950408889634f)

// prep kernel block ranges
#define NB_CONV 8192
#define NB_NORM 4096
#define NB_TGT  4096

// ---- persistent device scratch (chunk-tiled, pre-swizzled layouts) ----
__device__ __align__(16) __half g_xh[(size_t)BATCH * DIM];
__device__ __align__(16) __half g_fh[(size_t)NSAMP * DIM];
__device__ float g_partial[(size_t)BATCH * NTILES * 2];   // [row][nti][wn]
__device__ float g_tlogit[BATCH];
__device__ float g_bsum[32];
__device__ unsigned g_cnt;

// =============================== helpers ===============================
__device__ __forceinline__ uint32_t smem_u32(const void* p) {
    return (uint32_t)__cvta_generic_to_shared(p);
}
__device__ __forceinline__ uint32_t h2u(__half2 v) {
    return *reinterpret_cast<uint32_t*>(&v);
}
__device__ __forceinline__ void mbar_init(uint32_t mb, uint32_t cnt) {
    asm volatile("mbarrier.init.shared.b64 [%0], %1;" :: "r"(mb), "r"(cnt) : "memory");
}
__device__ __forceinline__ void mbar_wait(uint32_t mb, uint32_t parity) {
    asm volatile(
        "{\n\t.reg .pred P;\n"
        "W%=:\n\t"
        "mbarrier.try_wait.parity.shared.b64 P, [%0], %1, 0x989680;\n\t"
        "@!P bra W%=;\n\t}"
        :: "r"(mb), "r"(parity) : "memory");
}
#define MB_EXPECT(mb, b) \
    asm volatile("mbarrier.arrive.expect_tx.shared.b64 _, [%0], %1;" :: "r"(mb), "r"((uint32_t)(b)) : "memory")
#define MB_ARRIVE(mb) \
    asm volatile("mbarrier.arrive.shared.b64 _, [%0];" :: "r"(mb) : "memory")
__device__ __forceinline__ void bulk_g2s(uint32_t dst, const void* src, uint32_t bytes, uint32_t mb) {
    asm volatile(
        "cp.async.bulk.shared::cluster.global.mbarrier::complete_tx::bytes [%0], [%1], %2, [%3];"
        :: "r"(dst), "l"(src), "r"(bytes), "r"(mb) : "memory");
}
__device__ __forceinline__ void ldsm_x4(uint32_t& r0, uint32_t& r1, uint32_t& r2, uint32_t& r3,
                                        uint32_t addr) {
    asm volatile("ldmatrix.sync.aligned.m8n8.x4.shared.b16 {%0,%1,%2,%3}, [%4];"
                 : "=r"(r0), "=r"(r1), "=r"(r2), "=r"(r3) : "r"(addr));
}
__device__ __forceinline__ void mma_f16(float& c0, float& c1, float& c2, float& c3,
                                        uint32_t a0, uint32_t a1, uint32_t a2, uint32_t a3,
                                        uint32_t b0, uint32_t b1) {
    asm volatile(
        "mma.sync.aligned.m16n8k16.row.col.f32.f16.f16.f32 "
        "{%0,%1,%2,%3}, {%4,%5,%6,%7}, {%8,%9}, {%0,%1,%2,%3};"
        : "+f"(c0), "+f"(c1), "+f"(c2), "+f"(c3)
        : "r"(a0), "r"(a1), "r"(a2), "r"(a3), "r"(b0), "r"(b1));
}
// swizzled in-block byte offset for (row r, byte kb within 128B row)
__device__ __forceinline__ uint32_t swz(uint32_t r, uint32_t kb) {
    return r * 128u + (kb ^ ((r & 7u) << 4));
}

// ===================== Kernel 1: fused prep =====================
__global__ void kprep(const float* __restrict__ x, const float* __restrict__ feats,
                      const long long* __restrict__ ctgt) {
    int b = blockIdx.x;
    int t = threadIdx.x;  // 256

    if (b == 0 && t == 0) g_cnt = 0;

    if (b < NB_CONV) {
        size_t e0 = ((size_t)b * 256 + t) * 16;
        #pragma unroll
        for (int j = 0; j < 2; j++) {
            size_t e = e0 + j * 8;
            float4 a  = *reinterpret_cast<const float4*>(feats + e);
            float4 a2 = *reinterpret_cast<const float4*>(feats + e + 4);
            uint4 o;
            o.x = h2u(__floats2half2_rn(a.x, a.y));
            o.y = h2u(__floats2half2_rn(a.z, a.w));
            o.z = h2u(__floats2half2_rn(a2.x, a2.y));
            o.w = h2u(__floats2half2_rn(a2.z, a2.w));
            uint32_t n = (uint32_t)(e >> 10), col = (uint32_t)(e & 1023);
            uint32_t blk = (n >> 7) * NKC + (col >> 6);
            uint32_t off = blk * BLKB + swz(n & 127u, (col & 63u) * 2u);
            *reinterpret_cast<uint4*>(reinterpret_cast<char*>(g_fh) + off) = o;
        }
        return;
    }

    if (b < NB_CONV + NB_NORM) {
        int row = b - NB_CONV;
        const float4* xr = reinterpret_cast<const float4*>(x + (size_t)row * DIM);
        float4 v = xr[t];
        float ss = v.x * v.x + v.y * v.y + v.z * v.z + v.w * v.w;
        #pragma unroll
        for (int o = 16; o; o >>= 1) ss += __shfl_xor_sync(~0u, ss, o);
        __shared__ float sw1[8];
        if ((t & 31) == 0) sw1[t >> 5] = ss;
        __syncthreads();
        float tot = sw1[0] + sw1[1] + sw1[2] + sw1[3] + sw1[4] + sw1[5] + sw1[6] + sw1[7];
        float sc = rsqrtf(fmaxf(tot, 1e-24f));
        uint2 o;
        o.x = h2u(__floats2half2_rn(v.x * sc, v.y * sc));
        o.y = h2u(__floats2half2_rn(v.z * sc, v.w * sc));
        uint32_t r = (uint32_t)(row & 127);
        uint32_t blk = (uint32_t)((row >> 7) * NKC + (t >> 4));
        uint32_t off = blk * BLKB + swz(r, (uint32_t)(t & 15) * 8u);
        *reinterpret_cast<uint2*>(reinterpret_cast<char*>(g_xh) + off) = o;
        return;
    }

    {   // target logit, fully fp32, computes its own norm
        int row = b - NB_CONV - NB_NORM;
        long long tg64 = ctgt[row];
        int tg = (int)(tg64 < 0 ? 0 : (tg64 >= NSAMP ? NSAMP - 1 : tg64));
        float4 a  = reinterpret_cast<const float4*>(x + (size_t)row * DIM)[t];
        float4 bb = reinterpret_cast<const float4*>(feats + (size_t)tg * DIM)[t];
        float s  = a.x * bb.x + a.y * bb.y + a.z * bb.z + a.w * bb.w;
        float ss = a.x * a.x + a.y * a.y + a.z * a.z + a.w * a.w;
        #pragma unroll
        for (int o = 16; o; o >>= 1) {
            s  += __shfl_xor_sync(~0u, s, o);
            ss += __shfl_xor_sync(~0u, ss, o);
        }
        __shared__ float sw2[16];
        if ((t & 31) == 0) { sw2[t >> 5] = s; sw2[8 + (t >> 5)] = ss; }
        __syncthreads();
        if (t == 0) {
            float ts = 0.f, tss = 0.f;
            #pragma unroll
            for (int i = 0; i < 8; i++) { ts += sw2[i]; tss += sw2[8 + i]; }
            g_tlogit[row] = ts * rsqrtf(fmaxf(tss, 1e-24f)) * TEMP_INV;
        }
    }
}

// ============ Kernel 2: persistent HMMA, flat chunk stream across tiles ====
__device__ __forceinline__ void issue_chunk(int bid, int lt, uint32_t base, uint32_t mbd) {
    const int sf = lt % 3;
    const int tj = lt >> 4, ck = lt & 15;
    const int tile = bid + tj * GRID;
    const int m = tile & (MTILES - 1), nti = tile >> 5;
    const char* pA = reinterpret_cast<const char*>(g_xh) + ((size_t)m * NKC + ck) * BLKB;
    const char* pB = reinterpret_cast<const char*>(g_fh) + ((size_t)nti * NKC + ck) * BLKB;
    MB_EXPECT(mbd + sf * 8, STG);
    bulk_g2s(base + sf * STG,        pA, BLKB, mbd + sf * 8);
    bulk_g2s(base + sf * STG + BLKB, pB, BLKB, mbd + sf * 8);
}

__global__ __launch_bounds__(128, 2)
void kmain() {
    extern __shared__ __align__(1024) char dyn[];
    __shared__ __align__(8) uint64_t s_mb[6];   // [0..2] data, [3..5] free

    const int t = threadIdx.x;                // 128 threads = 4 warps (2m x 2n)
    const int lane = t & 31, warp = t >> 5;
    const int wm = warp >> 1;
    const int wn = warp & 1;
    const int bid = blockIdx.x;

    const int NTL = (TOTTILES - bid + GRID - 1) / GRID;   // tiles for this CTA
    const int L = NTL * NKC;                              // flat chunk count

    const uint32_t base = smem_u32(dyn);
    const uint32_t mbd = smem_u32(&s_mb[0]);
    const uint32_t mbf = smem_u32(&s_mb[3]);

    if (t == 0) {
        #pragma unroll
        for (int s = 0; s < 3; s++) { mbar_init(mbd + s * 8, 1); mbar_init(mbf + s * 8, 4); }
    }
    __syncthreads();

    // prologue: chunk c issued by warp c (c = c%3 ownership)
    if (warp < 2 && lane == 0) issue_chunk(bid, warp, base, mbd);

    const uint32_t a_r    = (uint32_t)(wm * 64 + (lane & 15));
    const uint32_t a_base = a_r * 128u;
    const uint32_t a_xor  = (a_r & 7u) << 4;
    const uint32_t a_cb   = (uint32_t)((lane >> 4) * 16);
    const uint32_t b_r    = (uint32_t)(wn * 64 + ((lane >> 4) * 8) + (lane & 7));
    const uint32_t b_base = b_r * 128u;
    const uint32_t b_xor  = (b_r & 7u) << 4;
    const uint32_t b_cb   = (uint32_t)(((lane >> 3) & 1) * 16);

    uint32_t a[2][4][4], b[2][4][4];

    // seed: wait chunk0 data, preload its ks0 frags into frag-buf 0
    mbar_wait(mbd, 0);
    {
        const uint32_t sA = base, sB = base + BLKB;
        #pragma unroll
        for (int mt = 0; mt < 4; mt++)
            ldsm_x4(a[0][mt][0], a[0][mt][1], a[0][mt][2], a[0][mt][3],
                    sA + a_base + mt * 2048u + (a_cb ^ a_xor));
        #pragma unroll
        for (int np = 0; np < 4; np++)
            ldsm_x4(b[0][np][0], b[0][np][1], b[0][np][2], b[0][np][3],
                    sB + b_base + np * 2048u + (b_cb ^ b_xor));
    }

    #pragma unroll 1
    for (int j = 0; j < NTL; j++) {
        const int tile = bid + j * GRID;
        const int m0 = (tile & (MTILES - 1)) * MT;
        const int nti = tile >> 5;

        float c[4][8][4];
        #pragma unroll
        for (int i = 0; i < 4; i++)
            #pragma unroll
            for (int jj = 0; jj < 8; jj++)
                #pragma unroll
                for (int q = 0; q < 4; q++) c[i][jj][q] = 0.f;

        #pragma unroll 1
        for (int ci = 0; ci < NKC; ci++) {
            const int li = j * NKC + ci;
            const int s = li % 3;
            // producer: warp (li+2)%3 refills its buffer with chunk li+2
            if (li + 2 < L) {
                const int sf = (li + 2) % 3;
                if (warp == sf && lane == 0) {
                    if (li >= 1) mbar_wait(mbf + sf * 8, (uint32_t)(((li - 1) / 3) & 1));
                    issue_chunk(bid, li + 2, base, mbd);
                }
            }
            const uint32_t sA = base + (uint32_t)s * STG;
            const uint32_t sB = sA + BLKB;

            #pragma unroll
            for (int ks = 0; ks < 4; ks++) {
                const int cur = ks & 1, nxt = cur ^ 1;
                if (ks < 3) {
                    const uint32_t kb = (uint32_t)((ks + 1) * 32);
                    #pragma unroll
                    for (int mt = 0; mt < 4; mt++)
                        ldsm_x4(a[nxt][mt][0], a[nxt][mt][1], a[nxt][mt][2], a[nxt][mt][3],
                                sA + a_base + mt * 2048u + ((kb + a_cb) ^ a_xor));
                    #pragma unroll
                    for (int np = 0; np < 4; np++)
                        ldsm_x4(b[nxt][np][0], b[nxt][np][1], b[nxt][np][2], b[nxt][np][3],
                                sB + b_base + np * 2048u + ((kb + b_cb) ^ b_xor));
                    if (ks == 2 && lane == 0) MB_ARRIVE(mbf + s * 8);   // buffer s reads issued
                } else if (li + 1 < L) {
                    // cross-chunk (and cross-tile) preload of next chunk's ks0
                    const int sn = (li + 1) % 3;
                    mbar_wait(mbd + sn * 8, (uint32_t)(((li + 1) / 3) & 1));
                    const uint32_t nA = base + (uint32_t)sn * STG;
                    const uint32_t nB = nA + BLKB;
                    #pragma unroll
                    for (int mt = 0; mt < 4; mt++)
                        ldsm_x4(a[nxt][mt][0], a[nxt][mt][1], a[nxt][mt][2], a[nxt][mt][3],
                                nA + a_base + mt * 2048u + (a_cb ^ a_xor));
                    #pragma unroll
                    for (int np = 0; np < 4; np++)
                        ldsm_x4(b[nxt][np][0], b[nxt][np][1], b[nxt][np][2], b[nxt][np][3],
                                nB + b_base + np * 2048u + (b_cb ^ b_xor));
                }
                #pragma unroll
                for (int mt = 0; mt < 4; mt++)
                    #pragma unroll
                    for (int np = 0; np < 4; np++) {
                        mma_f16(c[mt][2*np][0], c[mt][2*np][1], c[mt][2*np][2], c[mt][2*np][3],
                                a[cur][mt][0], a[cur][mt][1], a[cur][mt][2], a[cur][mt][3],
                                b[cur][np][0], b[cur][np][1]);
                        mma_f16(c[mt][2*np+1][0], c[mt][2*np+1][1], c[mt][2*np+1][2], c[mt][2*np+1][3],
                                a[cur][mt][0], a[cur][mt][1], a[cur][mt][2], a[cur][mt][3],
                                b[cur][np][2], b[cur][np][3]);
                    }
            }
        }

        // ---- epilogue for tile j (overlaps next tile's in-flight loads) ----
        #pragma unroll
        for (int mt = 0; mt < 4; mt++)
            #pragma unroll
            for (int h = 0; h < 2; h++) {
                float rs = 0.f;
                #pragma unroll
                for (int ntl = 0; ntl < 8; ntl++)
                    #pragma unroll
                    for (int jc = 0; jc < 2; jc++) {
                        float v = c[mt][ntl][h * 2 + jc];
                        float e;
                        asm("ex2.approx.f32 %0, %1;" : "=f"(e) : "f"(v * EXP_SCALE));
                        rs += e;
                    }
                rs += __shfl_xor_sync(~0u, rs, 1);
                rs += __shfl_xor_sync(~0u, rs, 2);
                if ((lane & 3) == 0) {
                    int row = m0 + wm * 64 + mt * 16 + (lane >> 2) + h * 8;
                    g_partial[((size_t)row * NTILES + nti) * 2 + wn] = rs;
                }
            }
    }
}

// ===================== Kernel 3: fused final reduce =====================
__global__ void kfin(float* __restrict__ out) {   // grid 32, block 256
    int bb = blockIdx.x, t = threadIdx.x, w = t >> 5, lane = t & 31;
    float acc = 0.f;
    for (int r0 = w; r0 < 128; r0 += 8) {
        int row = bb * 128 + r0;
        const float* p = g_partial + (size_t)row * NTILES * 2;
        float s = 0.f;
        #pragma unroll 4
        for (int i = lane; i < NTILES * 2; i += 32) s += p[i];
        #pragma unroll
        for (int o = 16; o; o >>= 1) s += __shfl_xor_sync(~0u, s, o);
        if (lane == 0) acc += logf(s) - g_tlogit[row];
    }
    __shared__ float sw[8];
    __shared__ int s_last;
    if (lane == 0) sw[w] = acc;
    __syncthreads();
    if (t == 0) {
        float v = 0.f;
        #pragma unroll
        for (int i = 0; i < 8; i++) v += sw[i];
        g_bsum[bb] = v;
        __threadfence();
        unsigned done = atomicAdd(&g_cnt, 1u);
        s_last = (done == 31u);
    }
    __syncthreads();
    if (s_last && t == 0) {
        float v = 0.f;
        #pragma unroll
        for (int i = 0; i < 32; i++) v += g_bsum[i];   // fixed order: deterministic
        out[0] = v * (1.0f / BATCH);
    }
}

// ===========================================================================
extern "C" void kernel_launch(void* const* d_in, const int* in_sizes, int n_in,
                              void* d_out, int out_size) {
    const float*     inputs = (const float*)d_in[0];
    const long long* ctgt   = (const long long*)d_in[2];
    const float*     feats  = (const float*)d_in[3];
    float* out = (float*)d_out;

    cudaFuncSetAttribute(kmain, cudaFuncAttributeMaxDynamicSharedMemorySize, SMEM_DYN);

    kprep<<<NB_CONV + NB_NORM + NB_TGT, 256>>>(inputs, feats, ctgt);
    kmain<<<GRID, 128, SMEM_DYN>>>();
    kfin<<<32, 256>>>(out);
}

// round 11
// speedup vs baseline: 1.6769x; 1.6769x over previous
#include <cuda_runtime.h>
#include <cuda_fp16.h>
#include <cstdint>

#define BATCH   4096
#define DIM     1024
#define NSAMP   32768
#define MT      128
#define NT      128
#define KC      64                   // K chunk (fp16) = 128B row
#define NKC     (DIM / KC)           // 16
#define MTILES  (BATCH / MT)         // 32
#define NTILES  (NSAMP / NT)         // 256
#define BLKB    16384                // one (tile, chunk) block: 128 rows x 128B
#define STG     (2 * BLKB)           // A + B per stage = 32KB
#define SMEM_DYN (3 * STG)           // 96KB
#define TEMP_INV 20.0f
#define EXP_SCALE (20.0f * 1.4426950408889634f)

// prep kernel block ranges
#define NB_CONV 8192                 // feats convert: 16 elems/thread
#define NB_NORM 4096
#define NB_TGT  4096

// ---- persistent device scratch (chunk-tiled, pre-swizzled layouts) ----
__device__ __align__(16) __half g_xh[(size_t)BATCH * DIM];
__device__ __align__(16) __half g_fh[(size_t)NSAMP * DIM];
__device__ float g_partial[(size_t)BATCH * NTILES * 2];   // [row][nti][wn]
__device__ float g_tlogit[BATCH];
__device__ float g_bsum[64];
__device__ unsigned g_cnt;

// =============================== helpers ===============================
__device__ __forceinline__ uint32_t smem_u32(const void* p) {
    return (uint32_t)__cvta_generic_to_shared(p);
}
__device__ __forceinline__ uint32_t h2u(__half2 v) {
    return *reinterpret_cast<uint32_t*>(&v);
}
__device__ __forceinline__ void mbar_init(uint32_t mb, uint32_t cnt) {
    asm volatile("mbarrier.init.shared.b64 [%0], %1;" :: "r"(mb), "r"(cnt) : "memory");
}
__device__ __forceinline__ void mbar_wait(uint32_t mb, uint32_t parity) {
    asm volatile(
        "{\n\t.reg .pred P;\n"
        "W%=:\n\t"
        "mbarrier.try_wait.parity.shared.b64 P, [%0], %1, 0x989680;\n\t"
        "@!P bra W%=;\n\t}"
        :: "r"(mb), "r"(parity) : "memory");
}
#define MB_EXPECT(mb, b) \
    asm volatile("mbarrier.arrive.expect_tx.shared.b64 _, [%0], %1;" :: "r"(mb), "r"((uint32_t)(b)) : "memory")
#define MB_ARRIVE(mb) \
    asm volatile("mbarrier.arrive.shared.b64 _, [%0];" :: "r"(mb) : "memory")
__device__ __forceinline__ void bulk_g2s(uint32_t dst, const void* src, uint32_t bytes, uint32_t mb) {
    asm volatile(
        "cp.async.bulk.shared::cluster.global.mbarrier::complete_tx::bytes [%0], [%1], %2, [%3];"
        :: "r"(dst), "l"(src), "r"(bytes), "r"(mb) : "memory");
}
__device__ __forceinline__ void ldsm_x4(uint32_t& r0, uint32_t& r1, uint32_t& r2, uint32_t& r3,
                                        uint32_t addr) {
    asm volatile("ldmatrix.sync.aligned.m8n8.x4.shared.b16 {%0,%1,%2,%3}, [%4];"
                 : "=r"(r0), "=r"(r1), "=r"(r2), "=r"(r3) : "r"(addr));
}
__device__ __forceinline__ void mma_f16(float& c0, float& c1, float& c2, float& c3,
                                        uint32_t a0, uint32_t a1, uint32_t a2, uint32_t a3,
                                        uint32_t b0, uint32_t b1) {
    asm volatile(
        "mma.sync.aligned.m16n8k16.row.col.f32.f16.f16.f32 "
        "{%0,%1,%2,%3}, {%4,%5,%6,%7}, {%8,%9}, {%0,%1,%2,%3};"
        : "+f"(c0), "+f"(c1), "+f"(c2), "+f"(c3)
        : "r"(a0), "r"(a1), "r"(a2), "r"(a3), "r"(b0), "r"(b1));
}
// swizzled in-block byte offset for (row r, byte kb within 128B row)
__device__ __forceinline__ uint32_t swz(uint32_t r, uint32_t kb) {
    return r * 128u + (kb ^ ((r & 7u) << 4));
}

// ===================== Kernel 1: fused prep =====================
__global__ void kprep(const float* __restrict__ x, const float* __restrict__ feats,
                      const long long* __restrict__ ctgt) {
    int b = blockIdx.x;
    int t = threadIdx.x;  // 256

    if (b == 0 && t == 0) g_cnt = 0;   // reset reduce counter every launch

    if (b < NB_CONV) {
        // 16 elems/thread, two 16B stores (swizzle is 16B-granular)
        size_t e0 = ((size_t)b * 256 + t) * 16;
        #pragma unroll
        for (int j = 0; j < 2; j++) {
            size_t e = e0 + j * 8;
            float4 a  = *reinterpret_cast<const float4*>(feats + e);
            float4 a2 = *reinterpret_cast<const float4*>(feats + e + 4);
            uint4 o;
            o.x = h2u(__floats2half2_rn(a.x, a.y));
            o.y = h2u(__floats2half2_rn(a.z, a.w));
            o.z = h2u(__floats2half2_rn(a2.x, a2.y));
            o.w = h2u(__floats2half2_rn(a2.z, a2.w));
            uint32_t n = (uint32_t)(e >> 10), col = (uint32_t)(e & 1023);
            uint32_t blk = (n >> 7) * NKC + (col >> 6);
            uint32_t off = blk * BLKB + swz(n & 127u, (col & 63u) * 2u);
            *reinterpret_cast<uint4*>(reinterpret_cast<char*>(g_fh) + off) = o;
        }
        return;
    }

    if (b < NB_CONV + NB_NORM) {
        int row = b - NB_CONV;
        const float4* xr = reinterpret_cast<const float4*>(x + (size_t)row * DIM);
        float4 v = xr[t];
        float ss = v.x * v.x + v.y * v.y + v.z * v.z + v.w * v.w;
        #pragma unroll
        for (int o = 16; o; o >>= 1) ss += __shfl_xor_sync(~0u, ss, o);
        __shared__ float sw1[8];
        if ((t & 31) == 0) sw1[t >> 5] = ss;
        __syncthreads();
        float tot = sw1[0] + sw1[1] + sw1[2] + sw1[3] + sw1[4] + sw1[5] + sw1[6] + sw1[7];
        float sc = rsqrtf(fmaxf(tot, 1e-24f));
        uint2 o;
        o.x = h2u(__floats2half2_rn(v.x * sc, v.y * sc));
        o.y = h2u(__floats2half2_rn(v.z * sc, v.w * sc));
        uint32_t r = (uint32_t)(row & 127);
        uint32_t blk = (uint32_t)((row >> 7) * NKC + (t >> 4));
        uint32_t off = blk * BLKB + swz(r, (uint32_t)(t & 15) * 8u);
        *reinterpret_cast<uint2*>(reinterpret_cast<char*>(g_xh) + off) = o;
        return;
    }

    {   // target logit, fully fp32, computes its own norm (128 active threads)
        int row = b - NB_CONV - NB_NORM;
        if (t >= 128) return;
        long long tg64 = ctgt[row];
        int tg = (int)(tg64 < 0 ? 0 : (tg64 >= NSAMP ? NSAMP - 1 : tg64));
        float4 a  = reinterpret_cast<const float4*>(x + (size_t)row * DIM)[t];
        float4 a1 = reinterpret_cast<const float4*>(x + (size_t)row * DIM)[t + 128];
        float4 bb = reinterpret_cast<const float4*>(feats + (size_t)tg * DIM)[t];
        float4 b1 = reinterpret_cast<const float4*>(feats + (size_t)tg * DIM)[t + 128];
        float s  = a.x * bb.x + a.y * bb.y + a.z * bb.z + a.w * bb.w
                 + a1.x * b1.x + a1.y * b1.y + a1.z * b1.z + a1.w * b1.w;
        float ss = a.x * a.x + a.y * a.y + a.z * a.z + a.w * a.w
                 + a1.x * a1.x + a1.y * a1.y + a1.z * a1.z + a1.w * a1.w;
        #pragma unroll
        for (int o = 16; o; o >>= 1) {
            s  += __shfl_xor_sync(~0u, s, o);
            ss += __shfl_xor_sync(~0u, ss, o);
        }
        __shared__ float sw2[8];
        if ((t & 31) == 0) { sw2[t >> 5] = s; sw2[4 + (t >> 5)] = ss; }
        __syncthreads();
        if (t == 0) {
            float ts  = sw2[0] + sw2[1] + sw2[2] + sw2[3];
            float tss = sw2[4] + sw2[5] + sw2[6] + sw2[7];
            g_tlogit[row] = ts * rsqrtf(fmaxf(tss, 1e-24f)) * TEMP_INV;
        }
    }
}

// ===================== Kernel 2: HMMA main, distributed producer ============
__global__ __launch_bounds__(128, 2)
void kmain() {
    extern __shared__ __align__(1024) char dyn[];
    __shared__ __align__(8) uint64_t s_mb[6];   // [0..2] data, [3..5] free

    const int t = threadIdx.x;                // 128 threads = 4 warps (2m x 2n)
    const int lane = t & 31, warp = t >> 5;
    const int wm = warp >> 1;
    const int wn = warp & 1;
    const int nti = blockIdx.y;

    const uint32_t base = smem_u32(dyn);
    const uint32_t mbd = smem_u32(&s_mb[0]);
    const uint32_t mbf = smem_u32(&s_mb[3]);

    const char* srcA = reinterpret_cast<const char*>(g_xh) + (size_t)blockIdx.x * NKC * BLKB;
    const char* srcB = reinterpret_cast<const char*>(g_fh) + (size_t)nti * NKC * BLKB;

    if (t == 0) {
        #pragma unroll
        for (int s = 0; s < 3; s++) { mbar_init(mbd + s * 8, 1); mbar_init(mbf + s * 8, 4); }
    }
    __syncthreads();

    // prologue: warps 0,1 issue chunks 0,1
    if (warp < 2 && lane == 0) {
        const int c = warp;
        MB_EXPECT(mbd + c * 8, STG);
        bulk_g2s(base + c * STG,        srcA + (size_t)c * BLKB, BLKB, mbd + c * 8);
        bulk_g2s(base + c * STG + BLKB, srcB + (size_t)c * BLKB, BLKB, mbd + c * 8);
    }

    const uint32_t a_r    = (uint32_t)(wm * 64 + (lane & 15));
    const uint32_t a_base = a_r * 128u;
    const uint32_t a_xor  = (a_r & 7u) << 4;
    const uint32_t a_cb   = (uint32_t)((lane >> 4) * 16);
    const uint32_t b_r    = (uint32_t)(wn * 64 + ((lane >> 4) * 8) + (lane & 7));
    const uint32_t b_base = b_r * 128u;
    const uint32_t b_xor  = (b_r & 7u) << 4;
    const uint32_t b_cb   = (uint32_t)(((lane >> 3) & 1) * 16);

    float c[4][8][4];
    #pragma unroll
    for (int i = 0; i < 4; i++)
        #pragma unroll
        for (int j = 0; j < 8; j++)
            #pragma unroll
            for (int q = 0; q < 4; q++) c[i][j][q] = 0.f;

    uint32_t a[2][4][4], b[2][4][4];

    // seed: wait chunk0, preload its ks0 frags into buf0
    mbar_wait(mbd, 0);
    {
        const uint32_t sA = base, sB = base + BLKB;
        #pragma unroll
        for (int mt = 0; mt < 4; mt++)
            ldsm_x4(a[0][mt][0], a[0][mt][1], a[0][mt][2], a[0][mt][3],
                    sA + a_base + mt * 2048u + (a_cb ^ a_xor));
        #pragma unroll
        for (int np = 0; np < 4; np++)
            ldsm_x4(b[0][np][0], b[0][np][1], b[0][np][2], b[0][np][3],
                    sB + b_base + np * 2048u + (b_cb ^ b_xor));
    }

    #pragma unroll 1
    for (int i = 0; i < NKC; i++) {
        const int s = i % 3;
        // distributed producer: warp sf refills buffer sf = (i+2)%3
        if (i + 2 < NKC) {
            const int sf = (i + 2) % 3;
            if (warp == sf && lane == 0) {
                if (i >= 1) mbar_wait(mbf + sf * 8, (uint32_t)(((i - 1) / 3) & 1));
                MB_EXPECT(mbd + sf * 8, STG);
                bulk_g2s(base + sf * STG,        srcA + (size_t)(i + 2) * BLKB, BLKB, mbd + sf * 8);
                bulk_g2s(base + sf * STG + BLKB, srcB + (size_t)(i + 2) * BLKB, BLKB, mbd + sf * 8);
            }
        }
        const uint32_t sA = base + (uint32_t)s * STG;
        const uint32_t sB = sA + BLKB;

        #pragma unroll
        for (int ks = 0; ks < 4; ks++) {
            const int cur = ks & 1, nxt = cur ^ 1;
            if (ks < 3) {
                const uint32_t kb = (uint32_t)((ks + 1) * 32);
                #pragma unroll
                for (int mt = 0; mt < 4; mt++)
                    ldsm_x4(a[nxt][mt][0], a[nxt][mt][1], a[nxt][mt][2], a[nxt][mt][3],
                            sA + a_base + mt * 2048u + ((kb + a_cb) ^ a_xor));
                #pragma unroll
                for (int np = 0; np < 4; np++)
                    ldsm_x4(b[nxt][np][0], b[nxt][np][1], b[nxt][np][2], b[nxt][np][3],
                            sB + b_base + np * 2048u + ((kb + b_cb) ^ b_xor));
                if (ks == 2 && lane == 0) MB_ARRIVE(mbf + s * 8);   // buffer s reads issued
            } else if (i + 1 < NKC) {
                const int sn = (i + 1) % 3;
                mbar_wait(mbd + sn * 8, (uint32_t)(((i + 1) / 3) & 1));
                const uint32_t nA = base + (uint32_t)sn * STG;
                const uint32_t nB = nA + BLKB;
                #pragma unroll
                for (int mt = 0; mt < 4; mt++)
                    ldsm_x4(a[nxt][mt][0], a[nxt][mt][1], a[nxt][mt][2], a[nxt][mt][3],
                            nA + a_base + mt * 2048u + (a_cb ^ a_xor));
                #pragma unroll
                for (int np = 0; np < 4; np++)
                    ldsm_x4(b[nxt][np][0], b[nxt][np][1], b[nxt][np][2], b[nxt][np][3],
                            nB + b_base + np * 2048u + (b_cb ^ b_xor));
            }
            #pragma unroll
            for (int mt = 0; mt < 4; mt++)
                #pragma unroll
                for (int np = 0; np < 4; np++) {
                    mma_f16(c[mt][2*np][0], c[mt][2*np][1], c[mt][2*np][2], c[mt][2*np][3],
                            a[cur][mt][0], a[cur][mt][1], a[cur][mt][2], a[cur][mt][3],
                            b[cur][np][0], b[cur][np][1]);
                    mma_f16(c[mt][2*np+1][0], c[mt][2*np+1][1], c[mt][2*np+1][2], c[mt][2*np+1][3],
                            a[cur][mt][0], a[cur][mt][1], a[cur][mt][2], a[cur][mt][3],
                            b[cur][np][2], b[cur][np][3]);
                }
        }
    }

    // ---- epilogue: exp-sum, shuffle-reduce, direct per-wn global write ----
    #pragma unroll
    for (int mt = 0; mt < 4; mt++)
        #pragma unroll
        for (int h = 0; h < 2; h++) {
            float rs = 0.f;
            #pragma unroll
            for (int ntl = 0; ntl < 8; ntl++)
                #pragma unroll
                for (int jc = 0; jc < 2; jc++) {
                    float v = c[mt][ntl][h * 2 + jc];
                    float e;
                    asm("ex2.approx.f32 %0, %1;" : "=f"(e) : "f"(v * EXP_SCALE));
                    rs += e;
                }
            rs += __shfl_xor_sync(~0u, rs, 1);
            rs += __shfl_xor_sync(~0u, rs, 2);
            if ((lane & 3) == 0) {
                int row = blockIdx.x * MT + wm * 64 + mt * 16 + (lane >> 2) + h * 8;
                g_partial[((size_t)row * NTILES + nti) * 2 + wn] = rs;
            }
        }
}

// ===================== Kernel 3: fused final reduce (64 blocks) =============
__global__ void kfin(float* __restrict__ out) {   // grid 64, block 256
    int bb = blockIdx.x, t = threadIdx.x, w = t >> 5, lane = t & 31;
    float acc = 0.f;
    for (int r0 = w; r0 < 64; r0 += 8) {
        int row = bb * 64 + r0;
        const float* p = g_partial + (size_t)row * NTILES * 2;
        float s = 0.f;
        #pragma unroll 4
        for (int i = lane; i < NTILES * 2; i += 32) s += p[i];
        #pragma unroll
        for (int o = 16; o; o >>= 1) s += __shfl_xor_sync(~0u, s, o);
        if (lane == 0) acc += logf(s) - g_tlogit[row];
    }
    __shared__ float sw[8];
    __shared__ int s_last;
    if (lane == 0) sw[w] = acc;
    __syncthreads();
    if (t == 0) {
        float v = 0.f;
        #pragma unroll
        for (int i = 0; i < 8; i++) v += sw[i];
        g_bsum[bb] = v;
        __threadfence();
        unsigned done = atomicAdd(&g_cnt, 1u);
        s_last = (done == 63u);
    }
    __syncthreads();
    if (s_last && t == 0) {
        float v = 0.f;
        #pragma unroll
        for (int i = 0; i < 64; i++) v += g_bsum[i];   // fixed order: deterministic
        out[0] = v * (1.0f / BATCH);
    }
}

// ===========================================================================
extern "C" void kernel_launch(void* const* d_in, const int* in_sizes, int n_in,
                              void* d_out, int out_size) {
    const float*     inputs = (const float*)d_in[0];
    const long long* ctgt   = (const long long*)d_in[2];
    const float*     feats  = (const float*)d_in[3];
    float* out = (float*)d_out;

    cudaFuncSetAttribute(kmain, cudaFuncAttributeMaxDynamicSharedMemorySize, SMEM_DYN);

    kprep<<<NB_CONV + NB_NORM + NB_TGT, 256>>>(inputs, feats, ctgt);
    dim3 grid(MTILES, NTILES);   // x = m (fast): CTAs sharing a B tile run together
    kmain<<<grid, 128, SMEM_DYN>>>();
    kfin<<<64, 256>>>(out);
}

// round 12
// speedup vs baseline: 1.6934x; 1.0098x over previous
#include <cuda_runtime.h>
#include <cuda_fp16.h>
#include <cstdint>

#define BATCH   4096
#define DIM     1024
#define NSAMP   32768
#define MT      128
#define NT      128
#define KC      64                   // K chunk (fp16) = 128B row
#define NKC     (DIM / KC)           // 16
#define MTILES  (BATCH / MT)         // 32
#define NTILES  (NSAMP / NT)         // 256
#define BLKB    16384                // one (tile, chunk) block: 128 rows x 128B
#define STG     (2 * BLKB)           // A + B per stage = 32KB
#define SMEM_DYN (3 * STG)           // 96KB
#define TPC     2                    // tiles per CTA (same nti)
#define LTOT    (TPC * NKC)          // 32 chunks per CTA
#define TEMP_INV 20.0f
#define EXP_SCALE (20.0f * 1.4426950408889634f)

// prep kernel block ranges
#define NB_CONV 8192                 // feats convert: 16 elems/thread
#define NB_NORM 4096
#define NB_TGT  4096

// ---- persistent device scratch (chunk-tiled, pre-swizzled layouts) ----
__device__ __align__(16) __half g_xh[(size_t)BATCH * DIM];
__device__ __align__(16) __half g_fh[(size_t)NSAMP * DIM];
__device__ float g_partial[(size_t)BATCH * NTILES * 2];   // [row][nti][wn]
__device__ float g_tlogit[BATCH];
__device__ float g_bsum[64];
__device__ unsigned g_cnt;

// =============================== helpers ===============================
__device__ __forceinline__ uint32_t smem_u32(const void* p) {
    return (uint32_t)__cvta_generic_to_shared(p);
}
__device__ __forceinline__ uint32_t h2u(__half2 v) {
    return *reinterpret_cast<uint32_t*>(&v);
}
__device__ __forceinline__ void mbar_init(uint32_t mb, uint32_t cnt) {
    asm volatile("mbarrier.init.shared.b64 [%0], %1;" :: "r"(mb), "r"(cnt) : "memory");
}
__device__ __forceinline__ void mbar_wait(uint32_t mb, uint32_t parity) {
    asm volatile(
        "{\n\t.reg .pred P;\n"
        "W%=:\n\t"
        "mbarrier.try_wait.parity.shared.b64 P, [%0], %1, 0x989680;\n\t"
        "@!P bra W%=;\n\t}"
        :: "r"(mb), "r"(parity) : "memory");
}
#define MB_EXPECT(mb, b) \
    asm volatile("mbarrier.arrive.expect_tx.shared.b64 _, [%0], %1;" :: "r"(mb), "r"((uint32_t)(b)) : "memory")
#define MB_ARRIVE(mb) \
    asm volatile("mbarrier.arrive.shared.b64 _, [%0];" :: "r"(mb) : "memory")
__device__ __forceinline__ void bulk_g2s(uint32_t dst, const void* src, uint32_t bytes, uint32_t mb) {
    asm volatile(
        "cp.async.bulk.shared::cluster.global.mbarrier::complete_tx::bytes [%0], [%1], %2, [%3];"
        :: "r"(dst), "l"(src), "r"(bytes), "r"(mb) : "memory");
}
__device__ __forceinline__ void ldsm_x4(uint32_t& r0, uint32_t& r1, uint32_t& r2, uint32_t& r3,
                                        uint32_t addr) {
    asm volatile("ldmatrix.sync.aligned.m8n8.x4.shared.b16 {%0,%1,%2,%3}, [%4];"
                 : "=r"(r0), "=r"(r1), "=r"(r2), "=r"(r3) : "r"(addr));
}
__device__ __forceinline__ void mma_f16(float& c0, float& c1, float& c2, float& c3,
                                        uint32_t a0, uint32_t a1, uint32_t a2, uint32_t a3,
                                        uint32_t b0, uint32_t b1) {
    asm volatile(
        "mma.sync.aligned.m16n8k16.row.col.f32.f16.f16.f32 "
        "{%0,%1,%2,%3}, {%4,%5,%6,%7}, {%8,%9}, {%0,%1,%2,%3};"
        : "+f"(c0), "+f"(c1), "+f"(c2), "+f"(c3)
        : "r"(a0), "r"(a1), "r"(a2), "r"(a3), "r"(b0), "r"(b1));
}
// swizzled in-block byte offset for (row r, byte kb within 128B row)
__device__ __forceinline__ uint32_t swz(uint32_t r, uint32_t kb) {
    return r * 128u + (kb ^ ((r & 7u) << 4));
}

// ===================== Kernel 1: fused prep =====================
__global__ void kprep(const float* __restrict__ x, const float* __restrict__ feats,
                      const long long* __restrict__ ctgt) {
    int b = blockIdx.x;
    int t = threadIdx.x;  // 256

    if (b == 0 && t == 0) g_cnt = 0;   // reset reduce counter every launch

    if (b < NB_CONV) {
        size_t e0 = ((size_t)b * 256 + t) * 16;
        #pragma unroll
        for (int j = 0; j < 2; j++) {
            size_t e = e0 + j * 8;
            float4 a  = *reinterpret_cast<const float4*>(feats + e);
            float4 a2 = *reinterpret_cast<const float4*>(feats + e + 4);
            uint4 o;
            o.x = h2u(__floats2half2_rn(a.x, a.y));
            o.y = h2u(__floats2half2_rn(a.z, a.w));
            o.z = h2u(__floats2half2_rn(a2.x, a2.y));
            o.w = h2u(__floats2half2_rn(a2.z, a2.w));
            uint32_t n = (uint32_t)(e >> 10), col = (uint32_t)(e & 1023);
            uint32_t blk = (n >> 7) * NKC + (col >> 6);
            uint32_t off = blk * BLKB + swz(n & 127u, (col & 63u) * 2u);
            *reinterpret_cast<uint4*>(reinterpret_cast<char*>(g_fh) + off) = o;
        }
        return;
    }

    if (b < NB_CONV + NB_NORM) {
        int row = b - NB_CONV;
        const float4* xr = reinterpret_cast<const float4*>(x + (size_t)row * DIM);
        float4 v = xr[t];
        float ss = v.x * v.x + v.y * v.y + v.z * v.z + v.w * v.w;
        #pragma unroll
        for (int o = 16; o; o >>= 1) ss += __shfl_xor_sync(~0u, ss, o);
        __shared__ float sw1[8];
        if ((t & 31) == 0) sw1[t >> 5] = ss;
        __syncthreads();
        float tot = sw1[0] + sw1[1] + sw1[2] + sw1[3] + sw1[4] + sw1[5] + sw1[6] + sw1[7];
        float sc = rsqrtf(fmaxf(tot, 1e-24f));
        uint2 o;
        o.x = h2u(__floats2half2_rn(v.x * sc, v.y * sc));
        o.y = h2u(__floats2half2_rn(v.z * sc, v.w * sc));
        uint32_t r = (uint32_t)(row & 127);
        uint32_t blk = (uint32_t)((row >> 7) * NKC + (t >> 4));
        uint32_t off = blk * BLKB + swz(r, (uint32_t)(t & 15) * 8u);
        *reinterpret_cast<uint2*>(reinterpret_cast<char*>(g_xh) + off) = o;
        return;
    }

    {   // target logit, fully fp32, computes its own norm (128 active threads)
        int row = b - NB_CONV - NB_NORM;
        if (t >= 128) return;
        long long tg64 = ctgt[row];
        int tg = (int)(tg64 < 0 ? 0 : (tg64 >= NSAMP ? NSAMP - 1 : tg64));
        float4 a  = reinterpret_cast<const float4*>(x + (size_t)row * DIM)[t];
        float4 a1 = reinterpret_cast<const float4*>(x + (size_t)row * DIM)[t + 128];
        float4 bb = reinterpret_cast<const float4*>(feats + (size_t)tg * DIM)[t];
        float4 b1 = reinterpret_cast<const float4*>(feats + (size_t)tg * DIM)[t + 128];
        float s  = a.x * bb.x + a.y * bb.y + a.z * bb.z + a.w * bb.w
                 + a1.x * b1.x + a1.y * b1.y + a1.z * b1.z + a1.w * b1.w;
        float ss = a.x * a.x + a.y * a.y + a.z * a.z + a.w * a.w
                 + a1.x * a1.x + a1.y * a1.y + a1.z * a1.z + a1.w * a1.w;
        #pragma unroll
        for (int o = 16; o; o >>= 1) {
            s  += __shfl_xor_sync(~0u, s, o);
            ss += __shfl_xor_sync(~0u, ss, o);
        }
        __shared__ float sw2[8];
        if ((t & 31) == 0) { sw2[t >> 5] = s; sw2[4 + (t >> 5)] = ss; }
        __syncthreads();
        if (t == 0) {
            float ts  = sw2[0] + sw2[1] + sw2[2] + sw2[3];
            float tss = sw2[4] + sw2[5] + sw2[6] + sw2[7];
            g_tlogit[row] = ts * rsqrtf(fmaxf(tss, 1e-24f)) * TEMP_INV;
        }
    }
}

// ======== Kernel 2: HMMA main, 2 tiles per CTA (same B), 3-buffer ring ======
__global__ __launch_bounds__(128, 2)
void kmain() {
    extern __shared__ __align__(1024) char dyn[];
    __shared__ __align__(8) uint64_t s_mb[6];   // [0..2] data, [3..5] free

    const int t = threadIdx.x;                // 128 threads = 4 warps (2m x 2n)
    const int lane = t & 31, warp = t >> 5;
    const int wm = warp >> 1;
    const int wn = warp & 1;
    const int nti = blockIdx.y;

    const uint32_t base = smem_u32(dyn);
    const uint32_t mbd = smem_u32(&s_mb[0]);
    const uint32_t mbf = smem_u32(&s_mb[3]);

    // chunk li -> tile j = li>>4 (m index 2*bx+j), ck = li&15; B shared across both tiles
    const char* srcA0 = reinterpret_cast<const char*>(g_xh) +
                        (size_t)(blockIdx.x * TPC) * NKC * BLKB;
    const char* srcB  = reinterpret_cast<const char*>(g_fh) + (size_t)nti * NKC * BLKB;

    if (t == 0) {
        #pragma unroll
        for (int s = 0; s < 3; s++) { mbar_init(mbd + s * 8, 1); mbar_init(mbf + s * 8, 4); }
    }
    __syncthreads();

    // prologue: warps 0,1 issue chunks 0,1 (both in tile 0)
    if (warp < 2 && lane == 0) {
        const int c = warp;
        MB_EXPECT(mbd + c * 8, STG);
        bulk_g2s(base + c * STG,        srcA0 + (size_t)c * BLKB, BLKB, mbd + c * 8);
        bulk_g2s(base + c * STG + BLKB, srcB  + (size_t)c * BLKB, BLKB, mbd + c * 8);
    }

    const uint32_t a_r    = (uint32_t)(wm * 64 + (lane & 15));
    const uint32_t a_base = a_r * 128u;
    const uint32_t a_xor  = (a_r & 7u) << 4;
    const uint32_t a_cb   = (uint32_t)((lane >> 4) * 16);
    const uint32_t b_r    = (uint32_t)(wn * 64 + ((lane >> 4) * 8) + (lane & 7));
    const uint32_t b_base = b_r * 128u;
    const uint32_t b_xor  = (b_r & 7u) << 4;
    const uint32_t b_cb   = (uint32_t)(((lane >> 3) & 1) * 16);

    uint32_t a[2][4][4], b[2][4][4];

    // seed: wait chunk0, preload its ks0 frags into frag-buf 0
    mbar_wait(mbd, 0);
    {
        const uint32_t sA = base, sB = base + BLKB;
        #pragma unroll
        for (int mt = 0; mt < 4; mt++)
            ldsm_x4(a[0][mt][0], a[0][mt][1], a[0][mt][2], a[0][mt][3],
                    sA + a_base + mt * 2048u + (a_cb ^ a_xor));
        #pragma unroll
        for (int np = 0; np < 4; np++)
            ldsm_x4(b[0][np][0], b[0][np][1], b[0][np][2], b[0][np][3],
                    sB + b_base + np * 2048u + (b_cb ^ b_xor));
    }

    #pragma unroll 1
    for (int j = 0; j < TPC; j++) {
        const int m0 = (blockIdx.x * TPC + j) * MT;

        float c[4][8][4];
        #pragma unroll
        for (int i = 0; i < 4; i++)
            #pragma unroll
            for (int jj = 0; jj < 8; jj++)
                #pragma unroll
                for (int q = 0; q < 4; q++) c[i][jj][q] = 0.f;

        #pragma unroll 1
        for (int ci = 0; ci < NKC; ci++) {
            const int li = (j << 4) | ci;
            const int s = li % 3;
            // producer: warp (li+2)%3 refills its buffer with chunk li+2
            if (li + 2 < LTOT) {
                const int lf = li + 2;
                const int sf = lf % 3;
                if (warp == sf && lane == 0) {
                    if (li >= 1) mbar_wait(mbf + sf * 8, (uint32_t)(((li - 1) / 3) & 1));
                    const char* pA = srcA0 + ((size_t)(lf >> 4) * NKC + (lf & 15)) * BLKB;
                    const char* pB = srcB  + (size_t)(lf & 15) * BLKB;
                    MB_EXPECT(mbd + sf * 8, STG);
                    bulk_g2s(base + sf * STG,        pA, BLKB, mbd + sf * 8);
                    bulk_g2s(base + sf * STG + BLKB, pB, BLKB, mbd + sf * 8);
                }
            }
            const uint32_t sA = base + (uint32_t)s * STG;
            const uint32_t sB = sA + BLKB;

            #pragma unroll
            for (int ks = 0; ks < 4; ks++) {
                const int cur = ks & 1, nxt = cur ^ 1;
                if (ks < 3) {
                    const uint32_t kb = (uint32_t)((ks + 1) * 32);
                    #pragma unroll
                    for (int mt = 0; mt < 4; mt++)
                        ldsm_x4(a[nxt][mt][0], a[nxt][mt][1], a[nxt][mt][2], a[nxt][mt][3],
                                sA + a_base + mt * 2048u + ((kb + a_cb) ^ a_xor));
                    #pragma unroll
                    for (int np = 0; np < 4; np++)
                        ldsm_x4(b[nxt][np][0], b[nxt][np][1], b[nxt][np][2], b[nxt][np][3],
                                sB + b_base + np * 2048u + ((kb + b_cb) ^ b_xor));
                    if (ks == 2 && lane == 0) MB_ARRIVE(mbf + s * 8);   // buffer s reads issued
                } else if (li + 1 < LTOT) {
                    // cross-chunk (and cross-tile) preload of next chunk's ks0
                    const int ln = li + 1;
                    const int sn = ln % 3;
                    mbar_wait(mbd + sn * 8, (uint32_t)((ln / 3) & 1));
                    const uint32_t nA = base + (uint32_t)sn * STG;
                    const uint32_t nB = nA + BLKB;
                    #pragma unroll
                    for (int mt = 0; mt < 4; mt++)
                        ldsm_x4(a[nxt][mt][0], a[nxt][mt][1], a[nxt][mt][2], a[nxt][mt][3],
                                nA + a_base + mt * 2048u + (a_cb ^ a_xor));
                    #pragma unroll
                    for (int np = 0; np < 4; np++)
                        ldsm_x4(b[nxt][np][0], b[nxt][np][1], b[nxt][np][2], b[nxt][np][3],
                                nB + b_base + np * 2048u + (b_cb ^ b_xor));
                }
                #pragma unroll
                for (int mt = 0; mt < 4; mt++)
                    #pragma unroll
                    for (int np = 0; np < 4; np++) {
                        mma_f16(c[mt][2*np][0], c[mt][2*np][1], c[mt][2*np][2], c[mt][2*np][3],
                                a[cur][mt][0], a[cur][mt][1], a[cur][mt][2], a[cur][mt][3],
                                b[cur][np][0], b[cur][np][1]);
                        mma_f16(c[mt][2*np+1][0], c[mt][2*np+1][1], c[mt][2*np+1][2], c[mt][2*np+1][3],
                                a[cur][mt][0], a[cur][mt][1], a[cur][mt][2], a[cur][mt][3],
                                b[cur][np][2], b[cur][np][3]);
                    }
            }
        }

        // ---- epilogue for tile j (overlaps next tile's in-flight loads) ----
        #pragma unroll
        for (int mt = 0; mt < 4; mt++)
            #pragma unroll
            for (int h = 0; h < 2; h++) {
                float rs = 0.f;
                #pragma unroll
                for (int ntl = 0; ntl < 8; ntl++)
                    #pragma unroll
                    for (int jc = 0; jc < 2; jc++) {
                        float v = c[mt][ntl][h * 2 + jc];
                        float e;
                        asm("ex2.approx.f32 %0, %1;" : "=f"(e) : "f"(v * EXP_SCALE));
                        rs += e;
                    }
                rs += __shfl_xor_sync(~0u, rs, 1);
                rs += __shfl_xor_sync(~0u, rs, 2);
                if ((lane & 3) == 0) {
                    int row = m0 + wm * 64 + mt * 16 + (lane >> 2) + h * 8;
                    g_partial[((size_t)row * NTILES + nti) * 2 + wn] = rs;
                }
            }
    }
}

// ===================== Kernel 3: fused final reduce (64 blocks) =============
__global__ void kfin(float* __restrict__ out) {   // grid 64, block 256
    int bb = blockIdx.x, t = threadIdx.x, w = t >> 5, lane = t & 31;
    float acc = 0.f;
    for (int r0 = w; r0 < 64; r0 += 8) {
        int row = bb * 64 + r0;
        const float* p = g_partial + (size_t)row * NTILES * 2;
        float s = 0.f;
        #pragma unroll 4
        for (int i = lane; i < NTILES * 2; i += 32) s += p[i];
        #pragma unroll
        for (int o = 16; o; o >>= 1) s += __shfl_xor_sync(~0u, s, o);
        if (lane == 0) acc += logf(s) - g_tlogit[row];
    }
    __shared__ float sw[8];
    __shared__ int s_last;
    if (lane == 0) sw[w] = acc;
    __syncthreads();
    if (t == 0) {
        float v = 0.f;
        #pragma unroll
        for (int i = 0; i < 8; i++) v += sw[i];
        g_bsum[bb] = v;
        __threadfence();
        unsigned done = atomicAdd(&g_cnt, 1u);
        s_last = (done == 63u);
    }
    __syncthreads();
    if (s_last && t == 0) {
        float v = 0.f;
        #pragma unroll
        for (int i = 0; i < 64; i++) v += g_bsum[i];   // fixed order: deterministic
        out[0] = v * (1.0f / BATCH);
    }
}

// ===========================================================================
extern "C" void kernel_launch(void* const* d_in, const int* in_sizes, int n_in,
                              void* d_out, int out_size) {
    const float*     inputs = (const float*)d_in[0];
    const long long* ctgt   = (const long long*)d_in[2];
    const float*     feats  = (const float*)d_in[3];
    float* out = (float*)d_out;

    cudaFuncSetAttribute(kmain, cudaFuncAttributeMaxDynamicSharedMemorySize, SMEM_DYN);

    kprep<<<NB_CONV + NB_NORM + NB_TGT, 256>>>(inputs, feats, ctgt);
    dim3 grid(MTILES / TPC, NTILES);   // (16, 256): x-major keeps B-tile sharers together
    kmain<<<grid, 128, SMEM_DYN>>>();
    kfin<<<64, 256>>>(out);
}